// round 5
// baseline (speedup 1.0000x reference)
#include <cuda_runtime.h>
#include <cuda_bf16.h>
#include <math.h>

#define NCAM 6
#define CIN_IMG 512
#define MID 256
#define DBINS 112
#define HH 32
#define WW 88
#define NPIX (HH*WW)          // 2816
#define NVOX (128*128*16)     // 262144

// ---------------- device scratch (no allocations allowed) ----------------
__device__ float g_x [NCAM*MID*NPIX];     // 17.3 MB
__device__ float g_y [NCAM*MID*NPIX];     // 17.3 MB
__device__ float g_dp[NCAM*DBINS*NPIX];   //  7.6 MB
__device__ float g_gate[NCAM*MID];

// packed f32x2 FMA (sm_103a): d = a*b + d, two fp32 lanes per issue slot
__device__ __forceinline__ void fma2(float2 &d, const float2 &a, const float2 &b) {
    unsigned long long &dd = reinterpret_cast<unsigned long long&>(const_cast<float2&>(d));
    const unsigned long long aa = reinterpret_cast<const unsigned long long&>(a);
    const unsigned long long bb = reinterpret_cast<const unsigned long long&>(b);
    asm("fma.rn.f32x2 %0, %1, %2, %0;" : "+l"(dd) : "l"(aa), "l"(bb));
}

// ---------------- gate / SE path (tiny) ----------------
__global__ void gate_kernel(const float* __restrict__ intr,
                            const float* __restrict__ w1, const float* __restrict__ b1,
                            const float* __restrict__ w2, const float* __restrict__ b2,
                            const float* __restrict__ rw, const float* __restrict__ rb,
                            const float* __restrict__ ew, const float* __restrict__ eb,
                            float* __restrict__ gate)
{
    int cam = blockIdx.x;
    int tid = threadIdx.x;   // 256
    __shared__ float sp_s;
    __shared__ float h[256], h2[256], t[256];

    if (tid == 0) {
        double A[4][8];
        for (int r = 0; r < 4; r++) {
            for (int c = 0; c < 4; c++) A[r][c] = (double)intr[cam*16 + r*4 + c];
            for (int c = 0; c < 4; c++) A[r][4+c] = (r == c) ? 1.0 : 0.0;
        }
        for (int col = 0; col < 4; col++) {
            int piv = col; double best = fabs(A[col][col]);
            for (int r = col+1; r < 4; r++)
                if (fabs(A[r][col]) > best) { best = fabs(A[r][col]); piv = r; }
            if (piv != col)
                for (int c = 0; c < 8; c++) { double tmp = A[col][c]; A[col][c] = A[piv][c]; A[piv][c] = tmp; }
            double d = A[col][col];
            for (int c = 0; c < 8; c++) A[col][c] /= d;
            for (int r = 0; r < 4; r++) if (r != col) {
                double f = A[r][col];
                for (int c = 0; c < 8; c++) A[r][c] -= f * A[col][c];
            }
        }
        double i00 = A[0][4], i11 = A[1][5];
        sp_s = (float)(1000.0 * sqrt(i00*i00 + i11*i11));
    }
    __syncthreads();
    float sp = sp_s;

    h[tid] = fmaxf(sp * w1[tid] + b1[tid], 0.f);
    __syncthreads();

    float s = b2[tid];
    for (int k = 0; k < 256; k++) s += h[k] * w2[k*256 + tid];
    h2[tid] = s;
    __syncthreads();

    s = rb[tid];
    for (int c = 0; c < 256; c++) s += rw[tid*256 + c] * h2[c];
    t[tid] = fmaxf(s, 0.f);
    __syncthreads();

    s = eb[tid];
    for (int c = 0; c < 256; c++) s += ew[tid*256 + c] * t[c];
    gate[cam*256 + tid] = 1.f / (1.f + __expf(-s));
}

// ---------------- 3x3 conv, direct, f32x2-packed, occupancy-tuned ----------------
// Block: 128 threads = 4 warps. Warp wq computes oc (kog*16 + wq*4 .. +3).
// Thread (ty,tx): row row0+ty, cols col0 + tx*8 .. +7  (8 px, as 4 f32x2 pairs).
// MODE 0: out = relu(conv*s+b) * gate[cam][oc]
// MODE 1: out = relu(conv*s+b)
// MODE 2: out = relu(res + conv*s+b)
template<int CIN, int MODE>
__global__ __launch_bounds__(128, 6)
void conv3x3_kernel(const float* __restrict__ in,          // [6][CIN][32][88]
                    const float* __restrict__ wgt,         // [256][CIN][3][3]
                    const float* __restrict__ scale,       // [256]
                    const float* __restrict__ bias,        // [256]
                    const float* __restrict__ gate_or_res,
                    float* __restrict__ out)               // [6][256][32][88]
{
    const int ct   = blockIdx.x;          // col tile: col0 = ct*32
    const int rt   = blockIdx.y;          // row tile: row0 = rt*8
    const int cam  = blockIdx.z >> 4;
    const int kog  = blockIdx.z & 15;     // oc group of 16: base kog*16
    const int tid  = threadIdx.x;         // 128
    const int wq   = tid >> 5;            // warp id = 4-oc subgroup
    const int lane = tid & 31;
    const int ty   = lane >> 2;           // 0..7 rows
    const int tx   = lane & 3;            // 0..3 -> cols tx*8..+7

    __shared__ __align__(16) float  s_in[8][10][34];   // [ci][r][c]  (stride 34: conflict-free LDS.64)
    __shared__ __align__(16) float2 s_w [16][8][9];    // [ko][ci][tap], duplicated (w,w)

    const int row0 = rt * 8;
    const int col0 = ct * 32;

    float2 acc[4][4];
    #pragma unroll
    for (int k = 0; k < 4; k++)
        #pragma unroll
        for (int p = 0; p < 4; p++) acc[k][p] = make_float2(0.f, 0.f);

    const float* inc = in  + cam * CIN * NPIX;
    const float* wc  = wgt + (kog*16) * CIN * 9;

    for (int ci0 = 0; ci0 < CIN; ci0 += 8) {
        // ---- cooperative loads ----
        const float* ip = inc + ci0 * NPIX;
        for (int idx = tid; idx < 8*10*34; idx += 128) {
            const int ci  = idx / 340;
            const int rem = idx - ci*340;
            const int r   = rem / 34;
            const int c   = rem - r*34;
            const int gh = row0 - 1 + r;
            const int gw = col0 - 1 + c;
            float v = 0.f;
            if (gh >= 0 && gh < HH && gw >= 0 && gw < WW)
                v = ip[ci * NPIX + gh*WW + gw];
            s_in[ci][r][c] = v;
        }
        #pragma unroll
        for (int j = 0; j < 9; j++) {                    // 16*8*9 = 1152 elems
            const int idx = tid + 128*j;
            const int ko  = idx / 72;
            const int rem = idx - ko*72;
            const float w = wc[ko * CIN * 9 + ci0 * 9 + rem];
            s_w[ko][0][rem] = make_float2(w, w);         // [8][9] contiguous: flat rem
        }
        __syncthreads();

        // ---- compute ----
        #pragma unroll
        for (int ci = 0; ci < 8; ci++) {
            #pragma unroll
            for (int r = 0; r < 3; r++) {
                // 10 input floats as 5 aligned pairs
                float2 v[5];
                const float* rowp = &s_in[ci][ty + r][tx * 8];
                #pragma unroll
                for (int j = 0; j < 5; j++)
                    v[j] = *reinterpret_cast<const float2*>(rowp + 2*j);
                // misaligned pairs for center tap
                float2 m[4];
                #pragma unroll
                for (int p = 0; p < 4; p++)
                    m[p] = make_float2(v[p].y, v[p+1].x);

                #pragma unroll
                for (int ko = 0; ko < 4; ko++) {
                    const float2* wp = &s_w[wq*4 + ko][ci][r*3];
                    const float2 w0 = wp[0], w1 = wp[1], w2 = wp[2];
                    #pragma unroll
                    for (int p = 0; p < 4; p++) {
                        fma2(acc[ko][p], v[p],   w0);
                        fma2(acc[ko][p], m[p],   w1);
                        fma2(acc[ko][p], v[p+1], w2);
                    }
                }
            }
        }
        __syncthreads();
    }

    // ---- epilogue ----
    const int orow = row0 + ty;
    #pragma unroll
    for (int ko = 0; ko < 4; ko++) {
        const int oc = kog*16 + wq*4 + ko;
        const float s = scale[oc];
        const float b = bias[oc];
        float gmul = 1.f;
        if (MODE == 0) gmul = gate_or_res[cam*256 + oc];
        #pragma unroll
        for (int p = 0; p < 4; p++) {
            const int ocol = col0 + tx*8 + 2*p;          // even; pair fully in/out (WW even)
            if (ocol < WW) {
                const int oidx = cam*MID*NPIX + oc*NPIX + orow*WW + ocol;
                float vx = acc[ko][p].x * s + b;
                float vy = acc[ko][p].y * s + b;
                if (MODE == 0) {
                    vx = fmaxf(vx, 0.f) * gmul;
                    vy = fmaxf(vy, 0.f) * gmul;
                } else if (MODE == 1) {
                    vx = fmaxf(vx, 0.f);
                    vy = fmaxf(vy, 0.f);
                } else {
                    const float2 res = *reinterpret_cast<const float2*>(&gate_or_res[oidx]);
                    vx = fmaxf(vx + res.x, 0.f);
                    vy = fmaxf(vy + res.y, 0.f);
                }
                *reinterpret_cast<float2*>(&out[oidx]) = make_float2(vx, vy);
            }
        }
    }
}

// ---------------- 1x1 depth conv + softmax over 112 bins ----------------
__global__ __launch_bounds__(128)
void depth_softmax_kernel(const float* __restrict__ x,   // [6][256][2816]
                          const float* __restrict__ w,   // [112][256]
                          const float* __restrict__ b,   // [112]
                          float* __restrict__ dp)        // [6][112][2816]
{
    const int pix = blockIdx.x;           // cam*2816 + p
    const int cam = pix / NPIX;
    const int p   = pix % NPIX;
    const int tid = threadIdx.x;          // 128

    __shared__ float sx[256];
    __shared__ float red[128];

    const float* xc = x + cam*MID*NPIX + p;
    sx[tid]       = xc[tid       * NPIX];
    sx[tid + 128] = xc[(tid+128) * NPIX];
    __syncthreads();

    float lg = -1e30f;
    if (tid < DBINS) {
        float s = b[tid];
        const float* wr = w + tid*256;
        #pragma unroll 8
        for (int c = 0; c < 256; c++) s = fmaf(sx[c], wr[c], s);
        lg = s;
    }
    red[tid] = lg; __syncthreads();
    for (int off = 64; off > 0; off >>= 1) {
        if (tid < off) red[tid] = fmaxf(red[tid], red[tid + off]);
        __syncthreads();
    }
    const float m = red[0];
    __syncthreads();

    float e = (tid < DBINS) ? __expf(lg - m) : 0.f;
    red[tid] = e; __syncthreads();
    for (int off = 64; off > 0; off >>= 1) {
        if (tid < off) red[tid] += red[tid + off];
        __syncthreads();
    }
    const float inv = 1.f / red[0];
    if (tid < DBINS)
        dp[(cam*DBINS + tid) * NPIX + p] = e * inv;
}

// ---------------- trilinear grid-sample + cam-sum + mask-normalize ----------------
__global__ __launch_bounds__(256)
void sample_kernel(const float* __restrict__ grid,   // [6][128][128][16][3]
                   const float* __restrict__ dp,     // [6][112][32][88]
                   float* __restrict__ out)          // [262144]
{
    const int v = blockIdx.x * blockDim.x + threadIdx.x;
    if (v >= NVOX) return;

    float agg = 0.f, mask = 0.f;
    #pragma unroll 1
    for (int cam = 0; cam < NCAM; cam++) {
        const float* g = grid + ((size_t)cam * NVOX + v) * 3;
        const float gx = g[0], gy = g[1], gz = g[2];
        const float ix = ((gx + 1.f) * 88.f  - 1.f) * 0.5f;
        const float iy = ((gy + 1.f) * 32.f  - 1.f) * 0.5f;
        const float iz = ((gz + 1.f) * 112.f - 1.f) * 0.5f;
        const float fx0 = floorf(ix), fy0 = floorf(iy), fz0 = floorf(iz);
        const float fx = ix - fx0, fy = iy - fy0, fz = iz - fz0;
        const int x0 = (int)fx0, y0 = (int)fy0, z0 = (int)fz0;
        const float* dc = dp + cam * DBINS * NPIX;
        #pragma unroll
        for (int dz = 0; dz < 2; dz++)
            #pragma unroll
            for (int dy = 0; dy < 2; dy++)
                #pragma unroll
                for (int dx = 0; dx < 2; dx++) {
                    const int xi = x0 + dx, yi = y0 + dy, zi = z0 + dz;
                    const float wv = (dx ? fx : 1.f - fx) * (dy ? fy : 1.f - fy) * (dz ? fz : 1.f - fz);
                    if (xi >= 0 && xi < WW && yi >= 0 && yi < HH && zi >= 0 && zi < DBINS) {
                        agg  += wv * dc[zi * NPIX + yi*WW + xi];
                        mask += wv;
                    }
                }
    }
    out[v] = (mask > 0.f) ? (agg / mask) : agg;
}

// ---------------- launch ----------------
extern "C" void kernel_launch(void* const* d_in, const int* in_sizes, int n_in,
                              void* d_out, int out_size)
{
    const float* img    = (const float*)d_in[0];
    const float* intr   = (const float*)d_in[1];
    const float* grid   = (const float*)d_in[2];
    const float* red_w  = (const float*)d_in[3];
    const float* red_s  = (const float*)d_in[4];
    const float* red_b  = (const float*)d_in[5];
    const float* mlp_w1 = (const float*)d_in[6];
    const float* mlp_b1 = (const float*)d_in[7];
    const float* mlp_w2 = (const float*)d_in[8];
    const float* mlp_b2 = (const float*)d_in[9];
    const float* se_rw  = (const float*)d_in[10];
    const float* se_rb  = (const float*)d_in[11];
    const float* se_ew  = (const float*)d_in[12];
    const float* se_eb  = (const float*)d_in[13];
    const float* bb_w   = (const float*)d_in[14];
    const float* bb_s   = (const float*)d_in[15];
    const float* bb_b   = (const float*)d_in[16];
    const float* dp_w   = (const float*)d_in[17];
    const float* dp_b   = (const float*)d_in[18];

    float *px, *py, *pdp, *pg;
    cudaGetSymbolAddress((void**)&px,  g_x);
    cudaGetSymbolAddress((void**)&py,  g_y);
    cudaGetSymbolAddress((void**)&pdp, g_dp);
    cudaGetSymbolAddress((void**)&pg,  g_gate);

    // 1) SE gate
    gate_kernel<<<NCAM, 256>>>(intr, mlp_w1, mlp_b1, mlp_w2, mlp_b2,
                               se_rw, se_rb, se_ew, se_eb, pg);

    // 2) reduce conv 512->256 (+scale/bias/relu, *gate)
    dim3 cgrid(3, 4, NCAM * 16);
    conv3x3_kernel<CIN_IMG, 0><<<cgrid, 128>>>(img, red_w, red_s, red_b, pg, px);

    // 3) three residual blocks
    const size_t WSTEP = (size_t)MID * MID * 9;
    for (int i = 0; i < 3; i++) {
        conv3x3_kernel<MID, 1><<<cgrid, 128>>>(px, bb_w + (size_t)(2*i)   * WSTEP,
                                               bb_s + (2*i)*MID,   bb_b + (2*i)*MID,
                                               nullptr, py);
        conv3x3_kernel<MID, 2><<<cgrid, 128>>>(py, bb_w + (size_t)(2*i+1) * WSTEP,
                                               bb_s + (2*i+1)*MID, bb_b + (2*i+1)*MID,
                                               px, px);
    }

    // 4) depth head + softmax
    depth_softmax_kernel<<<NCAM * NPIX, 128>>>(px, dp_w, dp_b, pdp);

    // 5) trilinear sample + camera sum + normalize
    sample_kernel<<<(NVOX + 255) / 256, 256>>>(grid, pdp, (float*)d_out);
}

// round 7
// speedup vs baseline: 2.0769x; 2.0769x over previous
#include <cuda_runtime.h>
#include <cuda_bf16.h>
#include <math.h>
#include <stdint.h>

#define NCAM 6
#define MID 256
#define DBINS 112
#define HH 32
#define WW 88
#define NPIX 2816
#define NVOX (128*128*16)
#define WHT 576            // weight half-tiles: 144 (L0) + 6*72

__device__ __align__(1024) float g_xf [NCAM*NPIX*MID];
__device__ __align__(1024) float g_dp [NCAM*DBINS*NPIX];
__device__ __align__(1024) float g_gate[NCAM*MID];
__device__ __align__(1024) __nv_bfloat16 g_imgh[NCAM*NPIX*512];
__device__ __align__(1024) __nv_bfloat16 g_imgl[NCAM*NPIX*512];
__device__ __align__(1024) __nv_bfloat16 g_xh[NCAM*NPIX*MID];
__device__ __align__(1024) __nv_bfloat16 g_xl[NCAM*NPIX*MID];
__device__ __align__(1024) __nv_bfloat16 g_yh[NCAM*NPIX*MID];
__device__ __align__(1024) __nv_bfloat16 g_yl[NCAM*NPIX*MID];
__device__ __align__(1024) __nv_bfloat16 g_Wh[WHT*128*64];
__device__ __align__(1024) __nv_bfloat16 g_Wl[WHT*128*64];

__device__ __forceinline__ uint32_t smem_u32(const void* p) {
    uint32_t a;
    asm("{ .reg .u64 t; cvta.to.shared.u64 t, %1; cvt.u32.u64 %0, t; }" : "=r"(a) : "l"(p));
    return a;
}
#define SW128(o) ((o) ^ (((o) >> 3) & 0x70))
#define LDM4(r0,r1,r2,r3,addr) \
    asm volatile("ldmatrix.sync.aligned.m8n8.x4.shared.b16 {%0,%1,%2,%3}, [%4];" \
        : "=r"(r0),"=r"(r1),"=r"(r2),"=r"(r3) : "r"(addr))
#define MMA(d,a,b0,b1) \
    asm volatile("mma.sync.aligned.m16n8k16.row.col.f32.bf16.bf16.f32 " \
        "{%0,%1,%2,%3},{%4,%5,%6,%7},{%8,%9},{%0,%1,%2,%3};" \
        : "+f"((d)[0]),"+f"((d)[1]),"+f"((d)[2]),"+f"((d)[3]) \
        : "r"((a)[0]),"r"((a)[1]),"r"((a)[2]),"r"((a)[3]),"r"(b0),"r"(b1))

// img [cam][512][px] f32 -> [cam][px][512] bf16 hi/lo
__global__ __launch_bounds__(256) void prep_img_kernel(const float* __restrict__ img)
{
    __shared__ float st[32][128];
    const int px0 = blockIdx.x * 128, cg = blockIdx.y, cam = blockIdx.z;
    const int tid = threadIdx.x;
    for (int i = tid; i < 32*128; i += 256) {
        const int c = i >> 7, p = i & 127;
        st[c][p] = img[((size_t)cam*512 + cg*32 + c)*NPIX + px0 + p];
    }
    __syncthreads();
    for (int i = tid; i < 128*32; i += 256) {
        const int p = i >> 5, c = i & 31;
        float v = st[c][p];
        __nv_bfloat16 h = __float2bfloat16(v);
        __nv_bfloat16 l = __float2bfloat16(v - __bfloat162float(h));
        const size_t o = ((size_t)(cam*NPIX + px0 + p))*512 + cg*32 + c;
        g_imgh[o] = h; g_imgl[o] = l;
    }
}

// weights -> split bf16, SW128-swizzled half-tiles [ht][128oc][64ci]
__global__ __launch_bounds__(256) void wtrans_kernel(const float* __restrict__ red_w,
                                                     const float* __restrict__ bb_w)
{
    const int idx = blockIdx.x*256 + threadIdx.x;
    if (idx >= WHT*128*64) return;
    const int r = idx >> 6, ci = idx & 63;
    const int ht = r >> 7, ocl = r & 127;
    float w;
    if (ht < 144) {
        const int g = ht >> 1, half = ht & 1, tap = g >> 3, cig = g & 7;
        w = red_w[((size_t)(half*128 + ocl)*512 + cig*64 + ci)*9 + tap];
    } else {
        const int h2 = ht - 144, layer = h2 / 72, rr = h2 % 72;
        const int g = rr >> 1, half = rr & 1, tap = g >> 2, cig = g & 3;
        w = bb_w[(size_t)layer*589824 + ((size_t)(half*128 + ocl)*256 + cig*64 + ci)*9 + tap];
    }
    __nv_bfloat16 h = __float2bfloat16(w);
    __nv_bfloat16 l = __float2bfloat16(w - __bfloat162float(h));
    const size_t off = (size_t)ht*16384 + SW128((uint32_t)(ocl*128 + ci*2));
    *(uint16_t*)((char*)g_Wh + off) = __bfloat16_as_ushort(h);
    *(uint16_t*)((char*)g_Wl + off) = __bfloat16_as_ushort(l);
}

__global__ void gate_kernel(const float* __restrict__ intr,
                            const float* __restrict__ w1, const float* __restrict__ b1,
                            const float* __restrict__ w2, const float* __restrict__ b2,
                            const float* __restrict__ rw, const float* __restrict__ rb,
                            const float* __restrict__ ew, const float* __restrict__ eb,
                            float* __restrict__ gate)
{
    int cam = blockIdx.x, tid = threadIdx.x;
    __shared__ float sp_s, h[256], h2[256], t[256];
    if (tid == 0) {
        double A[4][8];
        for (int r = 0; r < 4; r++) {
            for (int c = 0; c < 4; c++) A[r][c] = (double)intr[cam*16 + r*4 + c];
            for (int c = 0; c < 4; c++) A[r][4+c] = (r == c) ? 1.0 : 0.0;
        }
        for (int col = 0; col < 4; col++) {
            int piv = col; double best = fabs(A[col][col]);
            for (int r = col+1; r < 4; r++)
                if (fabs(A[r][col]) > best) { best = fabs(A[r][col]); piv = r; }
            if (piv != col)
                for (int c = 0; c < 8; c++) { double tmp = A[col][c]; A[col][c] = A[piv][c]; A[piv][c] = tmp; }
            double d = A[col][col];
            for (int c = 0; c < 8; c++) A[col][c] /= d;
            for (int r = 0; r < 4; r++) if (r != col) {
                double f = A[r][col];
                for (int c = 0; c < 8; c++) A[r][c] -= f * A[col][c];
            }
        }
        sp_s = (float)(1000.0 * sqrt(A[0][4]*A[0][4] + A[1][5]*A[1][5]));
    }
    __syncthreads();
    float sp = sp_s;
    h[tid] = fmaxf(sp * w1[tid] + b1[tid], 0.f);
    __syncthreads();
    float s = b2[tid];
    for (int k = 0; k < 256; k++) s += h[k] * w2[k*256 + tid];
    h2[tid] = s;
    __syncthreads();
    s = rb[tid];
    for (int c = 0; c < 256; c++) s += rw[tid*256 + c] * h2[c];
    t[tid] = fmaxf(s, 0.f);
    __syncthreads();
    s = eb[tid];
    for (int c = 0; c < 256; c++) s += ew[tid*256 + c] * t[c];
    gate[cam*256 + tid] = 1.f / (1.f + __expf(-s));
}

// HMMA conv: block = 128px x 128oc (8 warps, warp tile 32x64). Grid (22, 2, 6).
// MODE 0: relu(acc*s+b)*gate -> f32+split; 1: relu -> split only; 2: relu(res+..) -> f32+split
#define CONV_SMEM 67584
template<int CIN, int MODE>
__global__ void __launch_bounds__(256, 1)
conv_kernel(const __nv_bfloat16* __restrict__ inh, const __nv_bfloat16* __restrict__ inl,
            int aoff,
            const float* __restrict__ scale, const float* __restrict__ bias,
            const float* __restrict__ gate,  const float* res,
            float* outf, __nv_bfloat16* __restrict__ outh, __nv_bfloat16* __restrict__ outl)
{
    constexpr int CIG = CIN / 64, NCH = 9 * CIG;
    extern __shared__ __align__(1024) char smem[];
    float* s_sc = (float*)smem;
    float* s_bi = (float*)(smem + 512);
    float* s_gt = (float*)(smem + 1024);
    char* sA = smem + 2048;            // [128px][64k] bf16, hi; lo at +16384
    char* sB = smem + 2048 + 32768;    // [128oc][64k] bf16, hi; lo at +16384

    const int pxt = blockIdx.x, och = blockIdx.y, cam = blockIdx.z;
    const int tid = threadIdx.x, wid = tid >> 5, lane = tid & 31;
    const int wm = wid & 3, wn = wid >> 2;
    const int g = lane >> 2, tig = lane & 3;

    if (tid < 128) {
        s_sc[tid] = scale[och*128 + tid];
        s_bi[tid] = bias [och*128 + tid];
        s_gt[tid] = (MODE == 0) ? gate[cam*256 + och*128 + tid] : 0.f;
    }

    float acc[2][8][4];
    #pragma unroll
    for (int a = 0; a < 2; a++)
        #pragma unroll
        for (int b = 0; b < 8; b++)
            #pragma unroll
            for (int c = 0; c < 4; c++) acc[a][b][c] = 0.f;

    const uint32_t sbA = smem_u32(sA), sbB = smem_u32(sB);
    // ldmatrix lane->row/k mappings
    const int arow = wm*32 + (lane & 15);
    const int ak16 = (lane >> 4) << 4;                       // 0 or 16 bytes (k+8)
    const int brow = wn*64 + (lane & 7) + ((lane >> 4) << 3);
    const int bk16 = ((lane >> 3) & 1) << 4;

    for (int j = 0; j < NCH; j++) {
        const int tap = j / CIG, cig = j - tap*CIG;
        __syncthreads();
        // stage B: straight copy of pre-swizzled half-tile (16KB hi + 16KB lo)
        {
            const size_t ht = (size_t)(aoff + j*2 + och) * 16384;
            const uint4* srcH = (const uint4*)((const char*)g_Wh + ht);
            const uint4* srcL = (const uint4*)((const char*)g_Wl + ht);
            uint4* dH = (uint4*)sB; uint4* dL = (uint4*)(sB + 16384);
            #pragma unroll
            for (int t = 0; t < 4; t++) {
                dH[tid + 256*t] = srcH[tid + 256*t];
                dL[tid + 256*t] = srcL[tid + 256*t];
            }
        }
        // stage A: im2col gather 128px x 64ci, zero halo
        {
            const int dh = tap/3 - 1, dw = tap%3 - 1;
            #pragma unroll
            for (int t = 0; t < 4; t++) {
                const int u = tid + 256*t;
                const int px = u >> 3, q = u & 7;
                const int p = pxt*128 + px;
                const int h = p/88 + dh, w = p - (p/88)*88 + dw;
                uint4 vh = {0,0,0,0}, vl = {0,0,0,0};
                if ((unsigned)h < 32u && (unsigned)w < 88u) {
                    const size_t s0 = ((size_t)(cam*NPIX + h*88 + w))*CIN + cig*64 + q*8;
                    vh = *(const uint4*)(inh + s0);
                    vl = *(const uint4*)(inl + s0);
                }
                const uint32_t sw = SW128((uint32_t)(px*128 + q*16));
                *(uint4*)(sA + sw)         = vh;
                *(uint4*)(sA + 16384 + sw) = vl;
            }
        }
        __syncthreads();
        // compute: 4 ksteps of 16
        #pragma unroll
        for (int ks = 0; ks < 4; ks++) {
            uint32_t ah[2][4], al[2][4], bh[4][4], bl[4][4];
            #pragma unroll
            for (int mt = 0; mt < 2; mt++) {
                const uint32_t off = (uint32_t)((arow + mt*16)*128 + ks*32) + ak16;
                LDM4(ah[mt][0],ah[mt][1],ah[mt][2],ah[mt][3], sbA + SW128(off));
                LDM4(al[mt][0],al[mt][1],al[mt][2],al[mt][3], sbA + 16384 + SW128(off));
            }
            #pragma unroll
            for (int np = 0; np < 4; np++) {
                const uint32_t off = (uint32_t)((brow + np*16)*128 + ks*32) + bk16;
                LDM4(bh[np][0],bh[np][1],bh[np][2],bh[np][3], sbB + SW128(off));
                LDM4(bl[np][0],bl[np][1],bl[np][2],bl[np][3], sbB + 16384 + SW128(off));
            }
            #pragma unroll
            for (int mt = 0; mt < 2; mt++)
                #pragma unroll
                for (int np = 0; np < 4; np++) {
                    MMA(acc[mt][np*2],   ah[mt], bh[np][0], bh[np][1]);
                    MMA(acc[mt][np*2+1], ah[mt], bh[np][2], bh[np][3]);
                    MMA(acc[mt][np*2],   ah[mt], bl[np][0], bl[np][1]);
                    MMA(acc[mt][np*2+1], ah[mt], bl[np][2], bl[np][3]);
                    MMA(acc[mt][np*2],   al[mt], bh[np][0], bh[np][1]);
                    MMA(acc[mt][np*2+1], al[mt], bh[np][2], bh[np][3]);
                }
        }
    }

    // epilogue: direct global stores (D frag: rows px, cols oc)
    const int pxb = pxt*128 + wm*32;
    #pragma unroll
    for (int mt = 0; mt < 2; mt++)
        #pragma unroll
        for (int nt = 0; nt < 8; nt++) {
            const int ocl = wn*64 + nt*8 + 2*tig;
            const float2 sc = *(float2*)&s_sc[ocl];
            const float2 bi = *(float2*)&s_bi[ocl];
            #pragma unroll
            for (int r = 0; r < 2; r++) {
                const int px = pxb + mt*16 + g + r*8;
                float vx = acc[mt][nt][r*2]   * sc.x + bi.x;
                float vy = acc[mt][nt][r*2+1] * sc.y + bi.y;
                const size_t base = (size_t)(cam*NPIX + px)*256 + och*128 + ocl;
                if (MODE == 0) {
                    const float2 gt = *(float2*)&s_gt[ocl];
                    vx = fmaxf(vx, 0.f)*gt.x; vy = fmaxf(vy, 0.f)*gt.y;
                    *(float2*)&outf[base] = make_float2(vx, vy);
                } else if (MODE == 1) {
                    vx = fmaxf(vx, 0.f); vy = fmaxf(vy, 0.f);
                } else {
                    const float2 r0 = *(const float2*)&res[base];
                    vx = fmaxf(vx + r0.x, 0.f); vy = fmaxf(vy + r0.y, 0.f);
                    *(float2*)&outf[base] = make_float2(vx, vy);
                }
                const __nv_bfloat16 h0 = __float2bfloat16(vx), h1 = __float2bfloat16(vy);
                const uint32_t hp = (uint32_t)__bfloat16_as_ushort(h0)
                                  | ((uint32_t)__bfloat16_as_ushort(h1) << 16);
                const uint32_t lp =
                      (uint32_t)__bfloat16_as_ushort(__float2bfloat16(vx - __bfloat162float(h0)))
                    | ((uint32_t)__bfloat16_as_ushort(__float2bfloat16(vy - __bfloat162float(h1))) << 16);
                *(uint32_t*)&outh[base] = hp;
                *(uint32_t*)&outl[base] = lp;
            }
        }
}

__global__ __launch_bounds__(128)
void depth_softmax_kernel(const float* __restrict__ x,   // [6][2816][256]
                          const float* __restrict__ w, const float* __restrict__ b,
                          float* __restrict__ dp)
{
    const int pix = blockIdx.x, cam = pix / NPIX, p = pix % NPIX;
    const int tid = threadIdx.x;
    __shared__ float sx[256], red[128];
    const float* xc = x + (size_t)pix * 256;
    sx[tid] = xc[tid]; sx[tid+128] = xc[tid+128];
    __syncthreads();
    float lg = -1e30f;
    if (tid < DBINS) {
        float s = b[tid];
        const float* wr = w + tid*256;
        #pragma unroll 8
        for (int c = 0; c < 256; c++) s = fmaf(sx[c], wr[c], s);
        lg = s;
    }
    red[tid] = lg; __syncthreads();
    for (int off = 64; off > 0; off >>= 1) {
        if (tid < off) red[tid] = fmaxf(red[tid], red[tid+off]);
        __syncthreads();
    }
    const float m = red[0]; __syncthreads();
    float e = (tid < DBINS) ? __expf(lg - m) : 0.f;
    red[tid] = e; __syncthreads();
    for (int off = 64; off > 0; off >>= 1) {
        if (tid < off) red[tid] += red[tid+off];
        __syncthreads();
    }
    const float inv = 1.f / red[0];
    if (tid < DBINS) dp[((size_t)cam*DBINS + tid)*NPIX + p] = e * inv;
}

__global__ __launch_bounds__(256)
void sample_kernel(const float* __restrict__ grid, const float* __restrict__ dp,
                   float* __restrict__ out)
{
    const int v = blockIdx.x * blockDim.x + threadIdx.x;
    if (v >= NVOX) return;
    float agg = 0.f, mask = 0.f;
    #pragma unroll 1
    for (int cam = 0; cam < NCAM; cam++) {
        const float* g = grid + ((size_t)cam * NVOX + v) * 3;
        const float ix = ((g[0] + 1.f) * 88.f  - 1.f) * 0.5f;
        const float iy = ((g[1] + 1.f) * 32.f  - 1.f) * 0.5f;
        const float iz = ((g[2] + 1.f) * 112.f - 1.f) * 0.5f;
        const float fx0 = floorf(ix), fy0 = floorf(iy), fz0 = floorf(iz);
        const float fx = ix - fx0, fy = iy - fy0, fz = iz - fz0;
        const int x0 = (int)fx0, y0 = (int)fy0, z0 = (int)fz0;
        const float* dc = dp + (size_t)cam * DBINS * NPIX;
        #pragma unroll
        for (int dz = 0; dz < 2; dz++)
            #pragma unroll
            for (int dy = 0; dy < 2; dy++)
                #pragma unroll
                for (int dx = 0; dx < 2; dx++) {
                    const int xi = x0 + dx, yi = y0 + dy, zi = z0 + dz;
                    const float wv = (dx ? fx : 1.f-fx) * (dy ? fy : 1.f-fy) * (dz ? fz : 1.f-fz);
                    if (xi >= 0 && xi < WW && yi >= 0 && yi < HH && zi >= 0 && zi < DBINS) {
                        agg  += wv * dc[(size_t)zi*NPIX + yi*WW + xi];
                        mask += wv;
                    }
                }
    }
    out[v] = (mask > 0.f) ? (agg / mask) : agg;
}

extern "C" void kernel_launch(void* const* d_in, const int* in_sizes, int n_in,
                              void* d_out, int out_size)
{
    const float* img    = (const float*)d_in[0];
    const float* intr   = (const float*)d_in[1];
    const float* grid   = (const float*)d_in[2];
    const float* red_w  = (const float*)d_in[3];
    const float* red_s  = (const float*)d_in[4];
    const float* red_b  = (const float*)d_in[5];
    const float* mlp_w1 = (const float*)d_in[6];
    const float* mlp_b1 = (const float*)d_in[7];
    const float* mlp_w2 = (const float*)d_in[8];
    const float* mlp_b2 = (const float*)d_in[9];
    const float* se_rw  = (const float*)d_in[10];
    const float* se_rb  = (const float*)d_in[11];
    const float* se_ew  = (const float*)d_in[12];
    const float* se_eb  = (const float*)d_in[13];
    const float* bb_w   = (const float*)d_in[14];
    const float* bb_s   = (const float*)d_in[15];
    const float* bb_b   = (const float*)d_in[16];
    const float* dp_w   = (const float*)d_in[17];
    const float* dp_b   = (const float*)d_in[18];

    float *pxf, *pdp, *pg;
    __nv_bfloat16 *pih, *pil, *pxh, *pxl, *pyh, *pyl;
    cudaGetSymbolAddress((void**)&pxf, g_xf);
    cudaGetSymbolAddress((void**)&pdp, g_dp);
    cudaGetSymbolAddress((void**)&pg,  g_gate);
    cudaGetSymbolAddress((void**)&pih, g_imgh);
    cudaGetSymbolAddress((void**)&pil, g_imgl);
    cudaGetSymbolAddress((void**)&pxh, g_xh);
    cudaGetSymbolAddress((void**)&pxl, g_xl);
    cudaGetSymbolAddress((void**)&pyh, g_yh);
    cudaGetSymbolAddress((void**)&pyl, g_yl);

    cudaFuncSetAttribute(conv_kernel<512,0>, cudaFuncAttributeMaxDynamicSharedMemorySize, CONV_SMEM);
    cudaFuncSetAttribute(conv_kernel<256,1>, cudaFuncAttributeMaxDynamicSharedMemorySize, CONV_SMEM);
    cudaFuncSetAttribute(conv_kernel<256,2>, cudaFuncAttributeMaxDynamicSharedMemorySize, CONV_SMEM);

    gate_kernel<<<NCAM, 256>>>(intr, mlp_w1, mlp_b1, mlp_w2, mlp_b2,
                               se_rw, se_rb, se_ew, se_eb, pg);
    prep_img_kernel<<<dim3(22, 16, NCAM), 256>>>(img);
    wtrans_kernel<<<(WHT*128*64 + 255)/256, 256>>>(red_w, bb_w);

    dim3 cg(22, 2, NCAM);
    conv_kernel<512,0><<<cg, 256, CONV_SMEM>>>(pih, pil, 0, red_s, red_b, pg,
                                               nullptr, pxf, pxh, pxl);
    for (int i = 0; i < 3; i++) {
        conv_kernel<256,1><<<cg, 256, CONV_SMEM>>>(pxh, pxl, 144 + (2*i)*72,
            bb_s + (2*i)*MID, bb_b + (2*i)*MID, nullptr, nullptr, nullptr, pyh, pyl);
        conv_kernel<256,2><<<cg, 256, CONV_SMEM>>>(pyh, pyl, 144 + (2*i+1)*72,
            bb_s + (2*i+1)*MID, bb_b + (2*i+1)*MID, nullptr, pxf, pxf, pxh, pxl);
    }
    depth_softmax_kernel<<<NCAM * NPIX, 128>>>(pxf, dp_w, dp_b, pdp);
    sample_kernel<<<(NVOX + 255)/256, 256>>>(grid, pdp, (float*)d_out);
}

// round 8
// speedup vs baseline: 3.7782x; 1.8192x over previous
#include <cuda_runtime.h>
#include <cuda_bf16.h>
#include <math.h>
#include <stdint.h>

#define NCAM 6
#define MID 256
#define DBINS 112
#define HH 32
#define WW 88
#define NPIX 2816
#define NVOX (128*128*16)
#define WHT 576

__device__ __align__(1024) float g_xf [NCAM*NPIX*MID];
__device__ __align__(1024) float g_dp [NCAM*DBINS*NPIX];
__device__ __align__(1024) float g_gate[NCAM*MID];
__device__ __align__(1024) __nv_bfloat16 g_imgh[NCAM*NPIX*512];
__device__ __align__(1024) __nv_bfloat16 g_imgl[NCAM*NPIX*512];
__device__ __align__(1024) __nv_bfloat16 g_xh[NCAM*NPIX*MID];
__device__ __align__(1024) __nv_bfloat16 g_xl[NCAM*NPIX*MID];
__device__ __align__(1024) __nv_bfloat16 g_yh[NCAM*NPIX*MID];
__device__ __align__(1024) __nv_bfloat16 g_yl[NCAM*NPIX*MID];
__device__ __align__(1024) __nv_bfloat16 g_Wh[WHT*128*64];
__device__ __align__(1024) __nv_bfloat16 g_Wl[WHT*128*64];

__device__ __forceinline__ uint32_t smem_u32(const void* p) {
    uint32_t a;
    asm("{ .reg .u64 t; cvta.to.shared.u64 t, %1; cvt.u32.u64 %0, t; }" : "=r"(a) : "l"(p));
    return a;
}
#define SW128(o) ((o) ^ (((o) >> 3) & 0x70))
#define LDM4(r0,r1,r2,r3,addr) \
    asm volatile("ldmatrix.sync.aligned.m8n8.x4.shared.b16 {%0,%1,%2,%3}, [%4];" \
        : "=r"(r0),"=r"(r1),"=r"(r2),"=r"(r3) : "r"(addr))
#define MMA(d,a,b0,b1) \
    asm volatile("mma.sync.aligned.m16n8k16.row.col.f32.bf16.bf16.f32 " \
        "{%0,%1,%2,%3},{%4,%5,%6,%7},{%8,%9},{%0,%1,%2,%3};" \
        : "+f"((d)[0]),"+f"((d)[1]),"+f"((d)[2]),"+f"((d)[3]) \
        : "r"((a)[0]),"r"((a)[1]),"r"((a)[2]),"r"((a)[3]),"r"(b0),"r"(b1))
__device__ __forceinline__ void cpa16(uint32_t dst, const void* src, int sz) {
    asm volatile("cp.async.cg.shared.global [%0], [%1], 16, %2;" :: "r"(dst), "l"(src), "r"(sz) : "memory");
}
#define CPA_COMMIT() asm volatile("cp.async.commit_group;" ::: "memory")

__global__ __launch_bounds__(256) void prep_img_kernel(const float* __restrict__ img)
{
    __shared__ float st[32][128];
    const int px0 = blockIdx.x * 128, cg = blockIdx.y, cam = blockIdx.z;
    const int tid = threadIdx.x;
    for (int i = tid; i < 32*128; i += 256) {
        const int c = i >> 7, p = i & 127;
        st[c][p] = img[((size_t)cam*512 + cg*32 + c)*NPIX + px0 + p];
    }
    __syncthreads();
    for (int i = tid; i < 128*32; i += 256) {
        const int p = i >> 5, c = i & 31;
        float v = st[c][p];
        __nv_bfloat16 h = __float2bfloat16(v);
        __nv_bfloat16 l = __float2bfloat16(v - __bfloat162float(h));
        const size_t o = ((size_t)(cam*NPIX + px0 + p))*512 + cg*32 + c;
        g_imgh[o] = h; g_imgl[o] = l;
    }
}

__global__ __launch_bounds__(256) void wtrans_kernel(const float* __restrict__ red_w,
                                                     const float* __restrict__ bb_w)
{
    const int idx = blockIdx.x*256 + threadIdx.x;
    if (idx >= WHT*128*64) return;
    const int r = idx >> 6, ci = idx & 63;
    const int ht = r >> 7, ocl = r & 127;
    float w;
    if (ht < 144) {
        const int g = ht >> 1, half = ht & 1, tap = g >> 3, cig = g & 7;
        w = red_w[((size_t)(half*128 + ocl)*512 + cig*64 + ci)*9 + tap];
    } else {
        const int h2 = ht - 144, layer = h2 / 72, rr = h2 % 72;
        const int g = rr >> 1, half = rr & 1, tap = g >> 2, cig = g & 3;
        w = bb_w[(size_t)layer*589824 + ((size_t)(half*128 + ocl)*256 + cig*64 + ci)*9 + tap];
    }
    __nv_bfloat16 h = __float2bfloat16(w);
    __nv_bfloat16 l = __float2bfloat16(w - __bfloat162float(h));
    const size_t off = (size_t)ht*16384 + SW128((uint32_t)(ocl*128 + ci*2));
    *(uint16_t*)((char*)g_Wh + off) = __bfloat16_as_ushort(h);
    *(uint16_t*)((char*)g_Wl + off) = __bfloat16_as_ushort(l);
}

__global__ void gate_kernel(const float* __restrict__ intr,
                            const float* __restrict__ w1, const float* __restrict__ b1,
                            const float* __restrict__ w2, const float* __restrict__ b2,
                            const float* __restrict__ rw, const float* __restrict__ rb,
                            const float* __restrict__ ew, const float* __restrict__ eb,
                            float* __restrict__ gate)
{
    int cam = blockIdx.x, tid = threadIdx.x;
    __shared__ float sp_s, h[256], h2[256], t[256];
    if (tid == 0) {
        double A[4][8];
        for (int r = 0; r < 4; r++) {
            for (int c = 0; c < 4; c++) A[r][c] = (double)intr[cam*16 + r*4 + c];
            for (int c = 0; c < 4; c++) A[r][4+c] = (r == c) ? 1.0 : 0.0;
        }
        for (int col = 0; col < 4; col++) {
            int piv = col; double best = fabs(A[col][col]);
            for (int r = col+1; r < 4; r++)
                if (fabs(A[r][col]) > best) { best = fabs(A[r][col]); piv = r; }
            if (piv != col)
                for (int c = 0; c < 8; c++) { double tmp = A[col][c]; A[col][c] = A[piv][c]; A[piv][c] = tmp; }
            double d = A[col][col];
            for (int c = 0; c < 8; c++) A[col][c] /= d;
            for (int r = 0; r < 4; r++) if (r != col) {
                double f = A[r][col];
                for (int c = 0; c < 8; c++) A[r][c] -= f * A[col][c];
            }
        }
        sp_s = (float)(1000.0 * sqrt(A[0][4]*A[0][4] + A[1][5]*A[1][5]));
    }
    __syncthreads();
    float sp = sp_s;
    h[tid] = fmaxf(sp * w1[tid] + b1[tid], 0.f);
    __syncthreads();
    float s = b2[tid];
    for (int k = 0; k < 256; k++) s += h[k] * w2[k*256 + tid];
    h2[tid] = s;
    __syncthreads();
    s = rb[tid];
    for (int c = 0; c < 256; c++) s += rw[tid*256 + c] * h2[c];
    t[tid] = fmaxf(s, 0.f);
    __syncthreads();
    s = eb[tid];
    for (int c = 0; c < 256; c++) s += ew[tid*256 + c] * t[c];
    gate[cam*256 + tid] = 1.f / (1.f + __expf(-s));
}

// HMMA conv, cp.async double-buffered. Block 128px x 128oc, grid (22,2,6).
#define BUF 65536
#define CONV_SMEM (2048 + 2*BUF)
template<int CIN, int MODE>
__global__ void __launch_bounds__(256, 1)
conv_kernel(const __nv_bfloat16* __restrict__ inh, const __nv_bfloat16* __restrict__ inl,
            int aoff,
            const float* __restrict__ scale, const float* __restrict__ bias,
            const float* __restrict__ gate,  const float* res,
            float* outf, __nv_bfloat16* __restrict__ outh, __nv_bfloat16* __restrict__ outl)
{
    constexpr int CIG = CIN / 64, NCH = 9 * CIG;
    extern __shared__ __align__(1024) char smem[];
    float* s_sc = (float*)smem;
    float* s_bi = (float*)(smem + 512);
    float* s_gt = (float*)(smem + 1024);
    const uint32_t sb0 = smem_u32(smem) + 2048;    // buf b: A at sb0+b*BUF (32KB), B at +32768

    const int pxt = blockIdx.x, och = blockIdx.y, cam = blockIdx.z;
    const int tid = threadIdx.x, wid = tid >> 5, lane = tid & 31;
    const int wm = wid & 3, wn = wid >> 2;
    const int g = lane >> 2, tig = lane & 3;

    if (tid < 128) {
        s_sc[tid] = scale[och*128 + tid];
        s_bi[tid] = bias [och*128 + tid];
        s_gt[tid] = (MODE == 0) ? gate[cam*256 + och*128 + tid] : 0.f;
    }

    float acc[2][8][4];
    #pragma unroll
    for (int a = 0; a < 2; a++)
        #pragma unroll
        for (int b = 0; b < 8; b++)
            #pragma unroll
            for (int c = 0; c < 4; c++) acc[a][b][c] = 0.f;

    const int arow = wm*32 + (lane & 15);
    const int ak16 = (lane >> 4) << 4;
    const int brow = wn*64 + (lane & 7) + ((lane >> 4) << 3);
    const int bk16 = ((lane >> 3) & 1) << 4;

    auto stage = [&](int j, int b) {
        const uint32_t dA = sb0 + b*BUF, dB = dA + 32768;
        const size_t ht = (size_t)(aoff + j*2 + och) * 16384;
        const char* sH = (const char*)g_Wh + ht;
        const char* sL = (const char*)g_Wl + ht;
        #pragma unroll
        for (int t = 0; t < 4; t++) {
            const uint32_t o = (tid + 256*t) * 16;
            cpa16(dB + o,         sH + o, 16);
            cpa16(dB + 16384 + o, sL + o, 16);
        }
        const int tap = j / CIG, cig = j - tap*CIG;
        const int dh = tap/3 - 1, dw = tap%3 - 1;
        #pragma unroll
        for (int t = 0; t < 4; t++) {
            const int u = tid + 256*t;
            const int px = u >> 3, q = u & 7;
            const int p = pxt*128 + px;
            const int h = p/88 + dh, w = p - (p/88)*88 + dw;
            const bool ok = ((unsigned)h < 32u) & ((unsigned)w < 88u);
            const size_t s0 = ok ? (((size_t)(cam*NPIX + h*88 + w))*CIN + cig*64 + q*8) : 0;
            const int sz = ok ? 16 : 0;
            const uint32_t sw = SW128((uint32_t)(px*128 + q*16));
            cpa16(dA + sw,         inh + s0, sz);
            cpa16(dA + 16384 + sw, inl + s0, sz);
        }
        CPA_COMMIT();
    };

    stage(0, 0);
    for (int j = 0; j < NCH; j++) {
        const int b = j & 1;
        if (j + 1 < NCH) {
            stage(j + 1, 1 - b);
            asm volatile("cp.async.wait_group 1;" ::: "memory");
        } else {
            asm volatile("cp.async.wait_group 0;" ::: "memory");
        }
        __syncthreads();
        const uint32_t sbA = sb0 + b*BUF, sbB = sbA + 32768;
        #pragma unroll
        for (int ks = 0; ks < 4; ks++) {
            uint32_t ah[2][4], al[2][4], bh[4][4], bl[4][4];
            #pragma unroll
            for (int mt = 0; mt < 2; mt++) {
                const uint32_t off = (uint32_t)((arow + mt*16)*128 + ks*32) + ak16;
                LDM4(ah[mt][0],ah[mt][1],ah[mt][2],ah[mt][3], sbA + SW128(off));
                LDM4(al[mt][0],al[mt][1],al[mt][2],al[mt][3], sbA + 16384 + SW128(off));
            }
            #pragma unroll
            for (int np = 0; np < 4; np++) {
                const uint32_t off = (uint32_t)((brow + np*16)*128 + ks*32) + bk16;
                LDM4(bh[np][0],bh[np][1],bh[np][2],bh[np][3], sbB + SW128(off));
                LDM4(bl[np][0],bl[np][1],bl[np][2],bl[np][3], sbB + 16384 + SW128(off));
            }
            #pragma unroll
            for (int mt = 0; mt < 2; mt++)
                #pragma unroll
                for (int np = 0; np < 4; np++) {
                    MMA(acc[mt][np*2],   ah[mt], bh[np][0], bh[np][1]);
                    MMA(acc[mt][np*2+1], ah[mt], bh[np][2], bh[np][3]);
                    MMA(acc[mt][np*2],   ah[mt], bl[np][0], bl[np][1]);
                    MMA(acc[mt][np*2+1], ah[mt], bl[np][2], bl[np][3]);
                    MMA(acc[mt][np*2],   al[mt], bh[np][0], bh[np][1]);
                    MMA(acc[mt][np*2+1], al[mt], bh[np][2], bh[np][3]);
                }
        }
        __syncthreads();
    }

    const int pxb = pxt*128 + wm*32;
    #pragma unroll
    for (int mt = 0; mt < 2; mt++)
        #pragma unroll
        for (int nt = 0; nt < 8; nt++) {
            const int ocl = wn*64 + nt*8 + 2*tig;
            const float2 sc = *(float2*)&s_sc[ocl];
            const float2 bi = *(float2*)&s_bi[ocl];
            #pragma unroll
            for (int r = 0; r < 2; r++) {
                const int px = pxb + mt*16 + g + r*8;
                float vx = acc[mt][nt][r*2]   * sc.x + bi.x;
                float vy = acc[mt][nt][r*2+1] * sc.y + bi.y;
                const size_t base = (size_t)(cam*NPIX + px)*256 + och*128 + ocl;
                if (MODE == 0) {
                    const float2 gt = *(float2*)&s_gt[ocl];
                    vx = fmaxf(vx, 0.f)*gt.x; vy = fmaxf(vy, 0.f)*gt.y;
                    *(float2*)&outf[base] = make_float2(vx, vy);
                } else if (MODE == 1) {
                    vx = fmaxf(vx, 0.f); vy = fmaxf(vy, 0.f);
                } else {
                    const float2 r0 = *(const float2*)&res[base];
                    vx = fmaxf(vx + r0.x, 0.f); vy = fmaxf(vy + r0.y, 0.f);
                    *(float2*)&outf[base] = make_float2(vx, vy);
                }
                const __nv_bfloat16 h0 = __float2bfloat16(vx), h1 = __float2bfloat16(vy);
                const uint32_t hp = (uint32_t)__bfloat16_as_ushort(h0)
                                  | ((uint32_t)__bfloat16_as_ushort(h1) << 16);
                const uint32_t lp =
                      (uint32_t)__bfloat16_as_ushort(__float2bfloat16(vx - __bfloat162float(h0)))
                    | ((uint32_t)__bfloat16_as_ushort(__float2bfloat16(vy - __bfloat162float(h1))) << 16);
                *(uint32_t*)&outh[base] = hp;
                *(uint32_t*)&outl[base] = lp;
            }
        }
}

__global__ __launch_bounds__(128)
void depth_softmax_kernel(const float* __restrict__ x,
                          const float* __restrict__ w, const float* __restrict__ b,
                          float* __restrict__ dp)
{
    const int pix = blockIdx.x, cam = pix / NPIX, p = pix % NPIX;
    const int tid = threadIdx.x;
    __shared__ float sx[256], red[128];
    const float* xc = x + (size_t)pix * 256;
    sx[tid] = xc[tid]; sx[tid+128] = xc[tid+128];
    __syncthreads();
    float lg = -1e30f;
    if (tid < DBINS) {
        float a0 = 0.f, a1 = 0.f, a2 = 0.f, a3 = 0.f;
        const float* wr = w + tid*256;
        #pragma unroll 4
        for (int c = 0; c < 256; c += 4) {
            const float4 xv = *(const float4*)&sx[c];
            const float4 wv = *(const float4*)&wr[c];
            a0 = fmaf(xv.x, wv.x, a0); a1 = fmaf(xv.y, wv.y, a1);
            a2 = fmaf(xv.z, wv.z, a2); a3 = fmaf(xv.w, wv.w, a3);
        }
        lg = (a0 + a1) + (a2 + a3) + b[tid];
    }
    red[tid] = lg; __syncthreads();
    for (int off = 64; off > 0; off >>= 1) {
        if (tid < off) red[tid] = fmaxf(red[tid], red[tid+off]);
        __syncthreads();
    }
    const float m = red[0]; __syncthreads();
    float e = (tid < DBINS) ? __expf(lg - m) : 0.f;
    red[tid] = e; __syncthreads();
    for (int off = 64; off > 0; off >>= 1) {
        if (tid < off) red[tid] += red[tid+off];
        __syncthreads();
    }
    const float inv = 1.f / red[0];
    if (tid < DBINS) dp[((size_t)cam*DBINS + tid)*NPIX + p] = e * inv;
}

__global__ __launch_bounds__(256)
void sample_kernel(const float* __restrict__ grid, const float* __restrict__ dp,
                   float* __restrict__ out)
{
    const int v = blockIdx.x * blockDim.x + threadIdx.x;
    if (v >= NVOX) return;
    float agg = 0.f, mask = 0.f;
    #pragma unroll 1
    for (int cam = 0; cam < NCAM; cam++) {
        const float* g = grid + ((size_t)cam * NVOX + v) * 3;
        const float ix = ((g[0] + 1.f) * 88.f  - 1.f) * 0.5f;
        const float iy = ((g[1] + 1.f) * 32.f  - 1.f) * 0.5f;
        const float iz = ((g[2] + 1.f) * 112.f - 1.f) * 0.5f;
        const float fx0 = floorf(ix), fy0 = floorf(iy), fz0 = floorf(iz);
        const float fx = ix - fx0, fy = iy - fy0, fz = iz - fz0;
        const int x0 = (int)fx0, y0 = (int)fy0, z0 = (int)fz0;
        const float* dc = dp + (size_t)cam * DBINS * NPIX;
        #pragma unroll
        for (int dz = 0; dz < 2; dz++)
            #pragma unroll
            for (int dy = 0; dy < 2; dy++)
                #pragma unroll
                for (int dx = 0; dx < 2; dx++) {
                    const int xi = x0 + dx, yi = y0 + dy, zi = z0 + dz;
                    const float wv = (dx ? fx : 1.f-fx) * (dy ? fy : 1.f-fy) * (dz ? fz : 1.f-fz);
                    if (xi >= 0 && xi < WW && yi >= 0 && yi < HH && zi >= 0 && zi < DBINS) {
                        agg  += wv * dc[(size_t)zi*NPIX + yi*WW + xi];
                        mask += wv;
                    }
                }
    }
    out[v] = (mask > 0.f) ? (agg / mask) : agg;
}

extern "C" void kernel_launch(void* const* d_in, const int* in_sizes, int n_in,
                              void* d_out, int out_size)
{
    const float* img    = (const float*)d_in[0];
    const float* intr   = (const float*)d_in[1];
    const float* grid   = (const float*)d_in[2];
    const float* red_w  = (const float*)d_in[3];
    const float* red_s  = (const float*)d_in[4];
    const float* red_b  = (const float*)d_in[5];
    const float* mlp_w1 = (const float*)d_in[6];
    const float* mlp_b1 = (const float*)d_in[7];
    const float* mlp_w2 = (const float*)d_in[8];
    const float* mlp_b2 = (const float*)d_in[9];
    const float* se_rw  = (const float*)d_in[10];
    const float* se_rb  = (const float*)d_in[11];
    const float* se_ew  = (const float*)d_in[12];
    const float* se_eb  = (const float*)d_in[13];
    const float* bb_w   = (const float*)d_in[14];
    const float* bb_s   = (const float*)d_in[15];
    const float* bb_b   = (const float*)d_in[16];
    const float* dp_w   = (const float*)d_in[17];
    const float* dp_b   = (const float*)d_in[18];

    float *pxf, *pdp, *pg;
    __nv_bfloat16 *pih, *pil, *pxh, *pxl, *pyh, *pyl;
    cudaGetSymbolAddress((void**)&pxf, g_xf);
    cudaGetSymbolAddress((void**)&pdp, g_dp);
    cudaGetSymbolAddress((void**)&pg,  g_gate);
    cudaGetSymbolAddress((void**)&pih, g_imgh);
    cudaGetSymbolAddress((void**)&pil, g_imgl);
    cudaGetSymbolAddress((void**)&pxh, g_xh);
    cudaGetSymbolAddress((void**)&pxl, g_xl);
    cudaGetSymbolAddress((void**)&pyh, g_yh);
    cudaGetSymbolAddress((void**)&pyl, g_yl);

    cudaFuncSetAttribute(conv_kernel<512,0>, cudaFuncAttributeMaxDynamicSharedMemorySize, CONV_SMEM);
    cudaFuncSetAttribute(conv_kernel<256,1>, cudaFuncAttributeMaxDynamicSharedMemorySize, CONV_SMEM);
    cudaFuncSetAttribute(conv_kernel<256,2>, cudaFuncAttributeMaxDynamicSharedMemorySize, CONV_SMEM);

    gate_kernel<<<NCAM, 256>>>(intr, mlp_w1, mlp_b1, mlp_w2, mlp_b2,
                               se_rw, se_rb, se_ew, se_eb, pg);
    prep_img_kernel<<<dim3(22, 16, NCAM), 256>>>(img);
    wtrans_kernel<<<(WHT*128*64 + 255)/256, 256>>>(red_w, bb_w);

    dim3 cg(22, 2, NCAM);
    conv_kernel<512,0><<<cg, 256, CONV_SMEM>>>(pih, pil, 0, red_s, red_b, pg,
                                               nullptr, pxf, pxh, pxl);
    for (int i = 0; i < 3; i++) {
        conv_kernel<256,1><<<cg, 256, CONV_SMEM>>>(pxh, pxl, 144 + (2*i)*72,
            bb_s + (2*i)*MID, bb_b + (2*i)*MID, nullptr, nullptr, nullptr, pyh, pyl);
        conv_kernel<256,2><<<cg, 256, CONV_SMEM>>>(pyh, pyl, 144 + (2*i+1)*72,
            bb_s + (2*i+1)*MID, bb_b + (2*i+1)*MID, nullptr, pxf, pxf, pxh, pxl);
    }
    depth_softmax_kernel<<<NCAM * NPIX, 128>>>(pxf, dp_w, dp_b, pdp);
    sample_kernel<<<(NVOX + 255)/256, 256>>>(grid, pdp, (float*)d_out);
}